// round 7
// baseline (speedup 1.0000x reference)
#include <cuda_runtime.h>
#include <cstdint>

#define NPTS 400000
#define CCH  32
#define SX   480
#define SY   360
#define SZ   32
#define BB   2
#define LOOKUP_SIZE (BB*SX*SY*SZ)
#define EPSV 1e-5f

// ---- static scratch (no allocations allowed) ----
__device__ int   d_lookup[LOOKUP_SIZE];          // cell -> idx+1, 0 = empty (persistent)
__device__ __align__(16) float d_sums[64];       // [0:32) sum, [32:64) sumsq
__device__ float d_scale[CCH];
__device__ float d_shift[CCH];
__device__ int   d_cnt[8];                       // per-k pair counts (k != 4)
__device__ int2  d_pairs[8][NPTS];               // (out_pt, in_pt) per k
__device__ unsigned char d_flag[NPTS];           // point has >=1 valid neighbor

// ---- packed fp32x2 helpers ----
#define FMA2(d, a, b, c) \
    asm("fma.rn.f32x2 %0, %1, %2, %3;" : "=l"(d) : "l"(a), "l"(b), "l"(c))
#define PACK2(d, x) \
    asm("mov.b64 %0, {%1, %1};" : "=l"(d) : "r"(__float_as_uint(x)))
#define UNPACK2(lo, hi, a) \
    asm("mov.b64 {%0, %1}, %2;" : "=r"(lo), "=r"(hi) : "l"(a))

// ============================================================
// GEMV core from global feat row (used by neighbor kernel)
// ============================================================
__device__ __forceinline__ void gemv_accum(
    const float* __restrict__ frow,
    const unsigned long long* __restrict__ wbase,
    unsigned long long acc[16])
{
    const float4* fr = (const float4*)frow;
    float4 f0 = __ldg(fr + 0), f1 = __ldg(fr + 1);
    float4 f2 = __ldg(fr + 2), f3 = __ldg(fr + 3);
    float4 f4 = __ldg(fr + 4), f5 = __ldg(fr + 5);
    float4 f6 = __ldg(fr + 6), f7 = __ldg(fr + 7);
    float fv[32] = {
        f0.x, f0.y, f0.z, f0.w, f1.x, f1.y, f1.z, f1.w,
        f2.x, f2.y, f2.z, f2.w, f3.x, f3.y, f3.z, f3.w,
        f4.x, f4.y, f4.z, f4.w, f5.x, f5.y, f5.z, f5.w,
        f6.x, f6.y, f6.z, f6.w, f7.x, f7.y, f7.z, f7.w };
#pragma unroll
    for (int cin = 0; cin < 32; cin++) {
        unsigned long long bc;
        PACK2(bc, fv[cin]);
        const ulonglong2* wv = (const ulonglong2*)(wbase + cin * 16);
#pragma unroll
        for (int h = 0; h < 8; h++) {
            ulonglong2 wp = wv[h];
            FMA2(acc[2 * h],     bc, wp.x, acc[2 * h]);
            FMA2(acc[2 * h + 1], bc, wp.y, acc[2 * h + 1]);
        }
    }
}

// ============================================================
// 1. prep: reset pair counters + scatter lookup
// ============================================================
__global__ void prep_kernel(const int4* __restrict__ coords) {
    int i = blockIdx.x * blockDim.x + threadIdx.x;
    if (i < 8) d_cnt[i] = 0;
    if (i < NPTS) {
        int4 c = coords[i];
        d_lookup[((c.x * SX + c.y) * SY + c.z) * SZ + c.w] = i + 1;
    }
}

// ============================================================
// 2. probe: per-k pair lists + flags + zero flagged out rows
// ============================================================
__global__ __launch_bounds__(256) void probe_kernel(const int4* __restrict__ coords,
                                                    float* __restrict__ out) {
    __shared__ int s_wcnt[8][8];
    __shared__ int s_wbase[8][8];
    int tid  = threadIdx.x;
    int lane = tid & 31;
    int warp = tid >> 5;
    int pt = blockIdx.x * 256 + tid;
    bool act = pt < NPTS;

    int4 cc = act ? coords[pt] : make_int4(0, 1, 0, 1);
    int base = ((cc.x * SX + cc.y) * SY + cc.z) * SZ + cc.w;

    unsigned mask = 0;
    int nb[8];
#pragma unroll
    for (int k = 0; k < 9; k++) {
        if (k == 4) continue;
        int d0 = k / 3 - 1, d2 = k % 3 - 1;
        int n0 = cc.y + d0, n2 = cc.w + d2;
        bool valid = act && (n0 >= 0) && (n0 < SX) && (n2 >= 0) && (n2 < SZ);
        int idx = valid ? (base + d0 * (SY * SZ) + d2) : 0;
        int j = valid ? __ldg(&d_lookup[idx]) : 0;
        int ki = (k < 4) ? k : k - 1;
        nb[ki] = j - 1;
        if (j > 0) mask |= (1u << ki);
    }

    if (act) d_flag[pt] = (unsigned char)(mask ? 1 : 0);

    // cooperative zero of flagged rows (these receive red.adds)
    {
        unsigned fb = __ballot_sync(0xffffffffu, act && mask);
        int wbase_pt = blockIdx.x * 256 + warp * 32;
        while (fb) {
            int p = __ffs(fb) - 1;
            fb &= fb - 1;
            out[(long long)(wbase_pt + p) * CCH + lane] = 0.0f;
        }
    }

    unsigned bal[8];
#pragma unroll
    for (int ki = 0; ki < 8; ki++)
        bal[ki] = __ballot_sync(0xffffffffu, (mask >> ki) & 1u);
    if (lane == 0) {
#pragma unroll
        for (int ki = 0; ki < 8; ki++)
            s_wcnt[ki][warp] = __popc(bal[ki]);
    }
    __syncthreads();
    if (tid < 8) {
        int run = 0;
#pragma unroll
        for (int w = 0; w < 8; w++) {
            int c = s_wcnt[tid][w];
            s_wbase[tid][w] = run;
            run += c;
        }
        int g = atomicAdd(&d_cnt[tid], run);
#pragma unroll
        for (int w = 0; w < 8; w++)
            s_wbase[tid][w] += g;
    }
    __syncthreads();
#pragma unroll
    for (int ki = 0; ki < 8; ki++) {
        if ((mask >> ki) & 1u) {
            int rank = __popc(bal[ki] & ((1u << lane) - 1u));
            d_pairs[ki][s_wbase[ki][warp] + rank] = make_int2(pt, nb[ki]);
        }
    }
}

// ============================================================
// 3. neighbor conv: grid.y = ki, one thread per pair, uniform-k
// ============================================================
__global__ __launch_bounds__(256) void neighbor_kernel(
    const float* __restrict__ feat,
    const float* __restrict__ weight,
    float*       __restrict__ out)
{
    int ki = blockIdx.y;
    int k  = (ki < 4) ? ki : ki + 1;
    __shared__ unsigned long long w2[512];
    {
        const unsigned long long* ws =
            (const unsigned long long*)(weight + k * 1024);
        for (int i = threadIdx.x; i < 512; i += 256)
            w2[i] = ws[i];
    }
    __syncthreads();

    int n = d_cnt[ki];
    for (int p = blockIdx.x * 256 + threadIdx.x; p < n; p += gridDim.x * 256) {
        int2 pr = d_pairs[ki][p];
        unsigned long long acc[16];
#pragma unroll
        for (int q = 0; q < 16; q++) acc[q] = 0ull;
        gemv_accum(feat + (long long)pr.y * CCH, w2, acc);

        float* orow = out + (long long)pr.x * CCH;
#pragma unroll
        for (int h = 0; h < 8; h++) {
            unsigned int u0, u1, u2, u3;
            UNPACK2(u0, u1, acc[2 * h]);
            UNPACK2(u2, u3, acc[2 * h + 1]);
            asm volatile("red.global.add.v4.f32 [%0], {%1, %2, %3, %4};"
                         :: "l"(orow + 4 * h),
                            "f"(__uint_as_float(u0)), "f"(__uint_as_float(u1)),
                            "f"(__uint_as_float(u2)), "f"(__uint_as_float(u3))
                         : "memory");
        }
    }
}

// ============================================================
// 4. self conv + partial add + LeakyReLU + BN reduce
//    weights register-resident (loaded once/block); features via
//    LDS.128; thread = 2 couts x 8 points (interleaved rows)
// ============================================================
#define RSTR 36
#define BPTS 128
__global__ __launch_bounds__(256, 2) void selfleaky_kernel(
    const float* __restrict__ feat,
    const float* __restrict__ weight,
    float*       __restrict__ out)
{
    __shared__ float s_rows[BPTS * RSTR];        // 18.4 KB (in, then out)
    __shared__ unsigned char s_flag[BPTS];
    __shared__ float s_sum[32], s_sq[32];

    int tid  = threadIdx.x;
    int gbase = blockIdx.x * (BPTS * 8);         // float4 index base

    if (tid < 32) { s_sum[tid] = 0.0f; s_sq[tid] = 0.0f; }
    if (tid < BPTS) s_flag[tid] = d_flag[blockIdx.x * BPTS + tid];

    // ---- stage 128 feature rows, coalesced; NPTS%128==0: no guards ----
    {
        const float4* f4 = (const float4*)feat;
#pragma unroll
        for (int i = 0; i < 4; i++) {
            int idx = i * 256 + tid;
            float4 v = __ldg(f4 + gbase + idx);
            int r = idx >> 3;
            int c = (idx & 7) << 2;
            *(float4*)&s_rows[r * RSTR + c] = v;
        }
    }

    // ---- weights into registers: couts [2*c2, 2*c2+1], all 32 cin ----
    int c2 = tid & 15;
    int g  = tid >> 4;                            // point group 0..15
    unsigned long long wreg[32];
    {
        const float* wk = weight + 4 * 1024 + 2 * c2;
#pragma unroll
        for (int cin = 0; cin < 32; cin++)
            wreg[cin] = __ldg((const unsigned long long*)(wk + cin * 32));
    }
    __syncthreads();

    // ---- accumulate 8 points (rows g+16j), 2 passes of 4 ----
    unsigned long long acc[8];
#pragma unroll
    for (int q = 0; q < 8; q++) acc[q] = 0ull;

#pragma unroll
    for (int pass = 0; pass < 2; pass++) {
#pragma unroll
        for (int q = 0; q < 8; q++) {            // cin quad
            float4 fq[4];
#pragma unroll
            for (int j = 0; j < 4; j++) {
                int row = g + 16 * (4 * pass + j);
                fq[j] = *(const float4*)&s_rows[row * RSTR + 4 * q];
            }
#pragma unroll
            for (int j = 0; j < 4; j++) {
                unsigned long long b0, b1, b2, b3;
                PACK2(b0, fq[j].x);
                PACK2(b1, fq[j].y);
                PACK2(b2, fq[j].z);
                PACK2(b3, fq[j].w);
                int aj = 4 * pass + j;
                FMA2(acc[aj], b0, wreg[4 * q + 0], acc[aj]);
                FMA2(acc[aj], b1, wreg[4 * q + 1], acc[aj]);
                FMA2(acc[aj], b2, wreg[4 * q + 2], acc[aj]);
                FMA2(acc[aj], b3, wreg[4 * q + 3], acc[aj]);
            }
        }
    }
    __syncthreads();   // all feature reads complete before overwrite

    // ---- write results back into s_rows (same row layout) ----
#pragma unroll
    for (int j = 0; j < 8; j++) {
        unsigned int u0, u1;
        UNPACK2(u0, u1, acc[j]);
        float* dst = &s_rows[(g + 16 * j) * RSTR + 2 * c2];
        dst[0] = __uint_as_float(u0);
        dst[1] = __uint_as_float(u1);
    }
    __syncthreads();

    // ---- fused writeback: +partials, leaky, store, BN accumulate ----
    float bs0 = 0.f, bs1 = 0.f, bs2 = 0.f, bs3 = 0.f;
    float bq0 = 0.f, bq1 = 0.f, bq2 = 0.f, bq3 = 0.f;
    {
        float4* o4 = (float4*)out;
#pragma unroll
        for (int i = 0; i < 4; i++) {
            int idx = i * 256 + tid;
            int r = idx >> 3;
            int c = (idx & 7) << 2;
            float4 v = *(const float4*)&s_rows[r * RSTR + c];
            if (s_flag[r]) {
                float4 p = __ldg(o4 + gbase + idx);
                v.x += p.x; v.y += p.y; v.z += p.z; v.w += p.w;
            }
            v.x = fmaxf(v.x, 0.01f * v.x);
            v.y = fmaxf(v.y, 0.01f * v.y);
            v.z = fmaxf(v.z, 0.01f * v.z);
            v.w = fmaxf(v.w, 0.01f * v.w);
            o4[gbase + idx] = v;
            bs0 += v.x; bq0 = fmaf(v.x, v.x, bq0);
            bs1 += v.y; bq1 = fmaf(v.y, v.y, bq1);
            bs2 += v.z; bq2 = fmaf(v.z, v.z, bq2);
            bs3 += v.w; bq3 = fmaf(v.w, v.w, bq3);
        }
    }
    {
        int c0 = (tid & 7) * 4;
        atomicAdd(&s_sum[c0 + 0], bs0);
        atomicAdd(&s_sum[c0 + 1], bs1);
        atomicAdd(&s_sum[c0 + 2], bs2);
        atomicAdd(&s_sum[c0 + 3], bs3);
        atomicAdd(&s_sq[c0 + 0], bq0);
        atomicAdd(&s_sq[c0 + 1], bq1);
        atomicAdd(&s_sq[c0 + 2], bq2);
        atomicAdd(&s_sq[c0 + 3], bq3);
    }
    __syncthreads();
    if (tid < 32) {
        atomicAdd(&d_sums[tid],      s_sum[tid]);
        atomicAdd(&d_sums[32 + tid], s_sq[tid]);
    }
}

// ============================================================
// 5. finalize: scale/shift, re-zero accumulators for next replay
// ============================================================
__global__ void finalize_kernel(const float* __restrict__ gamma,
                                const float* __restrict__ beta) {
    int c = threadIdx.x;
    if (c < CCH) {
        const float invN = 1.0f / (float)NPTS;
        float mean = d_sums[c] * invN;
        float var  = d_sums[32 + c] * invN - mean * mean;
        float sc   = gamma[c] * rsqrtf(var + EPSV);
        d_scale[c] = sc;
        d_shift[c] = beta[c] - mean * sc;
        d_sums[c] = 0.0f;
        d_sums[32 + c] = 0.0f;
    }
}

// ============================================================
// 6. normalize in place: 4 independent float4 per thread (MLP=4)
// ============================================================
__global__ __launch_bounds__(256) void norm_kernel(float4* __restrict__ y) {
    __shared__ float4 s_sc[8], s_sh[8];
    if (threadIdx.x < 8) {
        s_sc[threadIdx.x] = ((const float4*)d_scale)[threadIdx.x];
        s_sh[threadIdx.x] = ((const float4*)d_shift)[threadIdx.x];
    }
    __syncthreads();
    int base = blockIdx.x * 1024;
#pragma unroll
    for (int i = 0; i < 4; i++) {
        int t = base + i * 256 + threadIdx.x;
        if (t < NPTS * 8) {
            int q = t & 7;
            float4 v = y[t];
            float4 sc = s_sc[q], sh = s_sh[q];
            v.x = fmaf(v.x, sc.x, sh.x);
            v.y = fmaf(v.y, sc.y, sh.y);
            v.z = fmaf(v.z, sc.z, sh.z);
            v.w = fmaf(v.w, sc.w, sh.w);
            y[t] = v;
        }
    }
}

// ============================================================
extern "C" void kernel_launch(void* const* d_in, const int* in_sizes, int n_in,
                              void* d_out, int out_size) {
    const float* feat   = (const float*)d_in[0];
    const int4*  coords = (const int4*)d_in[1];
    const float* weight = (const float*)d_in[2];
    const float* gamma  = (const float*)d_in[3];
    const float* beta   = (const float*)d_in[4];
    float* out = (float*)d_out;

    prep_kernel<<<(NPTS + 255) / 256, 256>>>(coords);
    probe_kernel<<<(NPTS + 255) / 256, 256>>>(coords, out);
    neighbor_kernel<<<dim3(64, 8), 256>>>(feat, weight, out);
    selfleaky_kernel<<<NPTS / BPTS, 256>>>(feat, weight, out);
    finalize_kernel<<<1, 32>>>(gamma, beta);
    norm_kernel<<<(NPTS * 8 + 1023) / 1024, 256>>>((float4*)out);
}

// round 8
// speedup vs baseline: 1.1313x; 1.1313x over previous
#include <cuda_runtime.h>
#include <cstdint>

#define NPTS 400000
#define CCH  32
#define SX   480
#define SY   360
#define SZ   32
#define BB   2
#define LOOKUP_SIZE (BB*SX*SY*SZ)
#define EPSV 1e-5f

// ---- static scratch (no allocations allowed) ----
__device__ int   d_lookup[LOOKUP_SIZE];          // cell -> idx+1, 0 = empty (persistent)
__device__ __align__(16) float d_sums[64];       // [0:32) sum, [32:64) sumsq
__device__ int   d_cnt[8];                       // per-k pair counts (k != 4)
__device__ int2  d_pairs[8][NPTS];               // (out_pt, in_pt) per k
__device__ unsigned char d_flag[NPTS];           // point has >=1 valid neighbor

// ---- packed fp32x2 helpers ----
#define FMA2(d, a, b, c) \
    asm("fma.rn.f32x2 %0, %1, %2, %3;" : "=l"(d) : "l"(a), "l"(b), "l"(c))
#define PACK2(d, x) \
    asm("mov.b64 %0, {%1, %1};" : "=l"(d) : "r"(__float_as_uint(x)))
#define UNPACK2(lo, hi, a) \
    asm("mov.b64 {%0, %1}, %2;" : "=r"(lo), "=r"(hi) : "l"(a))

// ============================================================
// GEMV core from global feat row (used by neighbor kernel)
// ============================================================
__device__ __forceinline__ void gemv_accum(
    const float* __restrict__ frow,
    const unsigned long long* __restrict__ wbase,
    unsigned long long acc[16])
{
    const float4* fr = (const float4*)frow;
    float4 f0 = __ldg(fr + 0), f1 = __ldg(fr + 1);
    float4 f2 = __ldg(fr + 2), f3 = __ldg(fr + 3);
    float4 f4 = __ldg(fr + 4), f5 = __ldg(fr + 5);
    float4 f6 = __ldg(fr + 6), f7 = __ldg(fr + 7);
    float fv[32] = {
        f0.x, f0.y, f0.z, f0.w, f1.x, f1.y, f1.z, f1.w,
        f2.x, f2.y, f2.z, f2.w, f3.x, f3.y, f3.z, f3.w,
        f4.x, f4.y, f4.z, f4.w, f5.x, f5.y, f5.z, f5.w,
        f6.x, f6.y, f6.z, f6.w, f7.x, f7.y, f7.z, f7.w };
#pragma unroll
    for (int cin = 0; cin < 32; cin++) {
        unsigned long long bc;
        PACK2(bc, fv[cin]);
        const ulonglong2* wv = (const ulonglong2*)(wbase + cin * 16);
#pragma unroll
        for (int h = 0; h < 8; h++) {
            ulonglong2 wp = wv[h];
            FMA2(acc[2 * h],     bc, wp.x, acc[2 * h]);
            FMA2(acc[2 * h + 1], bc, wp.y, acc[2 * h + 1]);
        }
    }
}

// ============================================================
// 1. prep: reset counters + BN sums, scatter lookup
// ============================================================
__global__ void prep_kernel(const int4* __restrict__ coords) {
    int i = blockIdx.x * blockDim.x + threadIdx.x;
    if (i < 8) d_cnt[i] = 0;
    if (i >= 8 && i < 72) d_sums[i - 8] = 0.0f;
    if (i < NPTS) {
        int4 c = coords[i];
        d_lookup[((c.x * SX + c.y) * SY + c.z) * SZ + c.w] = i + 1;
    }
}

// ============================================================
// 2. probe: per-k pair lists + flags + zero flagged out rows
// ============================================================
__global__ __launch_bounds__(256) void probe_kernel(const int4* __restrict__ coords,
                                                    float* __restrict__ out) {
    __shared__ int s_wcnt[8][8];
    __shared__ int s_wbase[8][8];
    int tid  = threadIdx.x;
    int lane = tid & 31;
    int warp = tid >> 5;
    int pt = blockIdx.x * 256 + tid;
    bool act = pt < NPTS;

    int4 cc = act ? coords[pt] : make_int4(0, 1, 0, 1);
    int base = ((cc.x * SX + cc.y) * SY + cc.z) * SZ + cc.w;

    unsigned mask = 0;
    int nb[8];
#pragma unroll
    for (int k = 0; k < 9; k++) {
        if (k == 4) continue;
        int d0 = k / 3 - 1, d2 = k % 3 - 1;
        int n0 = cc.y + d0, n2 = cc.w + d2;
        bool valid = act && (n0 >= 0) && (n0 < SX) && (n2 >= 0) && (n2 < SZ);
        int idx = valid ? (base + d0 * (SY * SZ) + d2) : 0;
        int j = valid ? __ldg(&d_lookup[idx]) : 0;
        int ki = (k < 4) ? k : k - 1;
        nb[ki] = j - 1;
        if (j > 0) mask |= (1u << ki);
    }

    if (act) d_flag[pt] = (unsigned char)(mask ? 1 : 0);

    // cooperative zero of flagged rows (these receive red.adds)
    {
        unsigned fb = __ballot_sync(0xffffffffu, act && mask);
        int wbase_pt = blockIdx.x * 256 + warp * 32;
        while (fb) {
            int p = __ffs(fb) - 1;
            fb &= fb - 1;
            out[(long long)(wbase_pt + p) * CCH + lane] = 0.0f;
        }
    }

    unsigned bal[8];
#pragma unroll
    for (int ki = 0; ki < 8; ki++)
        bal[ki] = __ballot_sync(0xffffffffu, (mask >> ki) & 1u);
    if (lane == 0) {
#pragma unroll
        for (int ki = 0; ki < 8; ki++)
            s_wcnt[ki][warp] = __popc(bal[ki]);
    }
    __syncthreads();
    if (tid < 8) {
        int run = 0;
#pragma unroll
        for (int w = 0; w < 8; w++) {
            int c = s_wcnt[tid][w];
            s_wbase[tid][w] = run;
            run += c;
        }
        int g = atomicAdd(&d_cnt[tid], run);
#pragma unroll
        for (int w = 0; w < 8; w++)
            s_wbase[tid][w] += g;
    }
    __syncthreads();
#pragma unroll
    for (int ki = 0; ki < 8; ki++) {
        if ((mask >> ki) & 1u) {
            int rank = __popc(bal[ki] & ((1u << lane) - 1u));
            d_pairs[ki][s_wbase[ki][warp] + rank] = make_int2(pt, nb[ki]);
        }
    }
}

// ============================================================
// 3. neighbor conv: grid.y = ki, one thread per pair, uniform-k
// ============================================================
__global__ __launch_bounds__(256) void neighbor_kernel(
    const float* __restrict__ feat,
    const float* __restrict__ weight,
    float*       __restrict__ out)
{
    int ki = blockIdx.y;
    int k  = (ki < 4) ? ki : ki + 1;
    __shared__ unsigned long long w2[512];
    {
        const unsigned long long* ws =
            (const unsigned long long*)(weight + k * 1024);
        for (int i = threadIdx.x; i < 512; i += 256)
            w2[i] = ws[i];
    }
    __syncthreads();

    int n = d_cnt[ki];
    for (int p = blockIdx.x * 256 + threadIdx.x; p < n; p += gridDim.x * 256) {
        int2 pr = d_pairs[ki][p];
        unsigned long long acc[16];
#pragma unroll
        for (int q = 0; q < 16; q++) acc[q] = 0ull;
        gemv_accum(feat + (long long)pr.y * CCH, w2, acc);

        float* orow = out + (long long)pr.x * CCH;
#pragma unroll
        for (int h = 0; h < 8; h++) {
            unsigned int u0, u1, u2, u3;
            UNPACK2(u0, u1, acc[2 * h]);
            UNPACK2(u2, u3, acc[2 * h + 1]);
            asm volatile("red.global.add.v4.f32 [%0], {%1, %2, %3, %4};"
                         :: "l"(orow + 4 * h),
                            "f"(__uint_as_float(u0)), "f"(__uint_as_float(u1)),
                            "f"(__uint_as_float(u2)), "f"(__uint_as_float(u3))
                         : "memory");
        }
    }
}

// ============================================================
// 4. self conv + partial add + LeakyReLU + BN reduce
//    thread = 8 couts x 2 points; weights broadcast LDS.128;
//    features LDS.128 per cin-quad; low regs -> 4 CTAs/SM
// ============================================================
#define RSTR 36
#define BPTS 128
__global__ __launch_bounds__(256, 4) void selfleaky_kernel(
    const float* __restrict__ feat,
    const float* __restrict__ weight,
    float*       __restrict__ out)
{
    __shared__ float s_rows[BPTS * RSTR];        // 18.4 KB (in, then out)
    __shared__ unsigned long long w2[512];       // 4 KB: W[4]
    __shared__ unsigned char s_flag[BPTS];
    __shared__ float s_sum[32], s_sq[32];

    int tid  = threadIdx.x;
    int gbase = blockIdx.x * (BPTS * 8);         // float4 index base

    {
        const unsigned long long* ws =
            (const unsigned long long*)(weight + 4 * 1024);
        for (int i = tid; i < 512; i += 256)
            w2[i] = ws[i];
        if (tid < 32) { s_sum[tid] = 0.0f; s_sq[tid] = 0.0f; }
        if (tid < BPTS) s_flag[tid] = d_flag[blockIdx.x * BPTS + tid];
    }

    // ---- stage 128 feature rows, coalesced (NPTS%128==0: no guards) ----
    {
        const float4* f4 = (const float4*)feat;
#pragma unroll
        for (int i = 0; i < 4; i++) {
            int idx = i * 256 + tid;
            float4 v = __ldg(f4 + gbase + idx);
            int r = idx >> 3;
            int c = (idx & 7) << 2;
            *(float4*)&s_rows[r * RSTR + c] = v;
        }
    }
    __syncthreads();

    // ---- gemm: q = cout quarter (couts [8q,8q+8)), s = point slot ----
    int q = tid >> 6;                 // uniform per warp -> broadcast weights
    int s = tid & 63;                 // points s and s+64

    unsigned long long acc[8];        // [0..3] point s, [4..7] point s+64
#pragma unroll
    for (int i = 0; i < 8; i++) acc[i] = 0ull;

    {
        const float* r0 = &s_rows[s * RSTR];
        const float* r1 = &s_rows[(s + 64) * RSTR];
        const ulonglong2* wq = (const ulonglong2*)&w2[4 * q];
#pragma unroll
        for (int t = 0; t < 8; t++) {               // cin quad
            float4 fq0 = *(const float4*)(r0 + 4 * t);
            float4 fq1 = *(const float4*)(r1 + 4 * t);
            float f0a[4] = { fq0.x, fq0.y, fq0.z, fq0.w };
            float f1a[4] = { fq1.x, fq1.y, fq1.z, fq1.w };
#pragma unroll
            for (int c = 0; c < 4; c++) {           // cin within quad
                int cin = 4 * t + c;
                ulonglong2 wa = wq[cin * 8 + 0];    // couts 8q..8q+3
                ulonglong2 wb = wq[cin * 8 + 1];    // couts 8q+4..8q+7
                unsigned long long b0, b1;
                PACK2(b0, f0a[c]);
                PACK2(b1, f1a[c]);
                FMA2(acc[0], b0, wa.x, acc[0]);
                FMA2(acc[1], b0, wa.y, acc[1]);
                FMA2(acc[2], b0, wb.x, acc[2]);
                FMA2(acc[3], b0, wb.y, acc[3]);
                FMA2(acc[4], b1, wa.x, acc[4]);
                FMA2(acc[5], b1, wa.y, acc[5]);
                FMA2(acc[6], b1, wb.x, acc[6]);
                FMA2(acc[7], b1, wb.y, acc[7]);
            }
        }
    }
    __syncthreads();   // all feature reads complete before overwrite

    // ---- write results back into s_rows (couts [8q,8q+8) contiguous) ----
#pragma unroll
    for (int j = 0; j < 2; j++) {
        float* dst = &s_rows[(s + 64 * j) * RSTR + 8 * q];
        unsigned int u0, u1, u2, u3, u4, u5, u6, u7;
        UNPACK2(u0, u1, acc[4 * j + 0]);
        UNPACK2(u2, u3, acc[4 * j + 1]);
        UNPACK2(u4, u5, acc[4 * j + 2]);
        UNPACK2(u6, u7, acc[4 * j + 3]);
        *(float4*)(dst + 0) = make_float4(__uint_as_float(u0), __uint_as_float(u1),
                                          __uint_as_float(u2), __uint_as_float(u3));
        *(float4*)(dst + 4) = make_float4(__uint_as_float(u4), __uint_as_float(u5),
                                          __uint_as_float(u6), __uint_as_float(u7));
    }
    __syncthreads();

    // ---- fused writeback: +partials, leaky, store, BN accumulate ----
    float bs0 = 0.f, bs1 = 0.f, bs2 = 0.f, bs3 = 0.f;
    float bq0 = 0.f, bq1 = 0.f, bq2 = 0.f, bq3 = 0.f;
    {
        float4* o4 = (float4*)out;
#pragma unroll
        for (int i = 0; i < 4; i++) {
            int idx = i * 256 + tid;
            int r = idx >> 3;
            int c = (idx & 7) << 2;
            float4 v = *(const float4*)&s_rows[r * RSTR + c];
            if (s_flag[r]) {
                float4 p = __ldg(o4 + gbase + idx);
                v.x += p.x; v.y += p.y; v.z += p.z; v.w += p.w;
            }
            v.x = fmaxf(v.x, 0.01f * v.x);
            v.y = fmaxf(v.y, 0.01f * v.y);
            v.z = fmaxf(v.z, 0.01f * v.z);
            v.w = fmaxf(v.w, 0.01f * v.w);
            o4[gbase + idx] = v;
            bs0 += v.x; bq0 = fmaf(v.x, v.x, bq0);
            bs1 += v.y; bq1 = fmaf(v.y, v.y, bq1);
            bs2 += v.z; bq2 = fmaf(v.z, v.z, bq2);
            bs3 += v.w; bq3 = fmaf(v.w, v.w, bq3);
        }
    }
    {
        int c0 = (tid & 7) * 4;
        atomicAdd(&s_sum[c0 + 0], bs0);
        atomicAdd(&s_sum[c0 + 1], bs1);
        atomicAdd(&s_sum[c0 + 2], bs2);
        atomicAdd(&s_sum[c0 + 3], bs3);
        atomicAdd(&s_sq[c0 + 0], bq0);
        atomicAdd(&s_sq[c0 + 1], bq1);
        atomicAdd(&s_sq[c0 + 2], bq2);
        atomicAdd(&s_sq[c0 + 3], bq3);
    }
    __syncthreads();
    if (tid < 32) {
        atomicAdd(&d_sums[tid],      s_sum[tid]);
        atomicAdd(&d_sums[32 + tid], s_sq[tid]);
    }
}

// ============================================================
// 5. normalize in place; scale/shift computed per block (fused finalize)
// ============================================================
__global__ __launch_bounds__(256) void norm_kernel(float4* __restrict__ y,
                                                   const float* __restrict__ gamma,
                                                   const float* __restrict__ beta) {
    __shared__ float s_sc[32], s_sh[32];
    if (threadIdx.x < 32) {
        int c = threadIdx.x;
        const float invN = 1.0f / (float)NPTS;
        float sum = __ldg(&d_sums[c]);
        float sq  = __ldg(&d_sums[32 + c]);
        float mean = sum * invN;
        float var  = sq * invN - mean * mean;
        float sc   = __ldg(&gamma[c]) * rsqrtf(var + EPSV);
        s_sc[c] = sc;
        s_sh[c] = __ldg(&beta[c]) - mean * sc;
    }
    __syncthreads();
    int base = blockIdx.x * 1024;
#pragma unroll
    for (int i = 0; i < 4; i++) {
        int t = base + i * 256 + threadIdx.x;    // total = 3.2M, grid exact
        int c0 = (t & 7) * 4;
        float4 v = y[t];
        v.x = fmaf(v.x, s_sc[c0 + 0], s_sh[c0 + 0]);
        v.y = fmaf(v.y, s_sc[c0 + 1], s_sh[c0 + 1]);
        v.z = fmaf(v.z, s_sc[c0 + 2], s_sh[c0 + 2]);
        v.w = fmaf(v.w, s_sc[c0 + 3], s_sh[c0 + 3]);
        y[t] = v;
    }
}

// ============================================================
extern "C" void kernel_launch(void* const* d_in, const int* in_sizes, int n_in,
                              void* d_out, int out_size) {
    const float* feat   = (const float*)d_in[0];
    const int4*  coords = (const int4*)d_in[1];
    const float* weight = (const float*)d_in[2];
    const float* gamma  = (const float*)d_in[3];
    const float* beta   = (const float*)d_in[4];
    float* out = (float*)d_out;

    prep_kernel<<<(NPTS + 255) / 256, 256>>>(coords);
    probe_kernel<<<(NPTS + 255) / 256, 256>>>(coords, out);
    neighbor_kernel<<<dim3(64, 8), 256>>>(feat, weight, out);
    selfleaky_kernel<<<NPTS / BPTS, 256>>>(feat, weight, out);
    norm_kernel<<<NPTS * 8 / 1024, 256>>>((float4*)out, gamma, beta);
}

// round 10
// speedup vs baseline: 1.2069x; 1.0668x over previous
#include <cuda_runtime.h>
#include <cuda_bf16.h>
#include <cstdint>

#define NPTS 400000
#define CCH  32
#define SX   480
#define SY   360
#define SZ   32
#define BB   2
#define LOOKUP_SIZE (BB*SX*SY*SZ)
#define EPSV 1e-5f

// ---- static scratch (no allocations allowed) ----
__device__ int   d_lookup[LOOKUP_SIZE];          // cell -> idx+1, 0 = empty (persistent)
__device__ __align__(16) float d_sums[64];       // [0:32) sum, [32:64) sumsq
__device__ int   d_cnt[8];                       // per-k pair counts (k != 4)
__device__ int2  d_pairs[8][NPTS];               // (out_pt, in_pt) per k
__device__ unsigned char d_flag[NPTS];           // point has >=1 valid neighbor

// ---- packed fp32x2 helpers (neighbor kernel) ----
#define FMA2(d, a, b, c) \
    asm("fma.rn.f32x2 %0, %1, %2, %3;" : "=l"(d) : "l"(a), "l"(b), "l"(c))
#define PACK2(d, x) \
    asm("mov.b64 %0, {%1, %1};" : "=l"(d) : "r"(__float_as_uint(x)))
#define UNPACK2(lo, hi, a) \
    asm("mov.b64 {%0, %1}, %2;" : "=r"(lo), "=r"(hi) : "l"(a))

__device__ __forceinline__ uint32_t smem_u32(const void* p) {
    uint32_t a;
    asm("{ .reg .u64 t; cvta.to.shared.u64 t, %1; cvt.u32.u64 %0, t; }"
        : "=r"(a) : "l"(p));
    return a;
}

#define LDSM_X4(r0, r1, r2, r3, addr) \
    asm volatile("ldmatrix.sync.aligned.m8n8.x4.shared.b16 {%0,%1,%2,%3}, [%4];" \
                 : "=r"(r0), "=r"(r1), "=r"(r2), "=r"(r3) : "r"(addr))

#define MMA_BF16(c, a0, a1, a2, a3, b0, b1) \
    asm volatile("mma.sync.aligned.m16n8k16.row.col.f32.bf16.bf16.f32 " \
                 "{%0,%1,%2,%3}, {%4,%5,%6,%7}, {%8,%9}, {%0,%1,%2,%3};" \
                 : "+f"(c[0]), "+f"(c[1]), "+f"(c[2]), "+f"(c[3]) \
                 : "r"(a0), "r"(a1), "r"(a2), "r"(a3), "r"(b0), "r"(b1))

// ============================================================
// GEMV core from global feat row (used by neighbor kernel)
// ============================================================
__device__ __forceinline__ void gemv_accum(
    const float* __restrict__ frow,
    const unsigned long long* __restrict__ wbase,
    unsigned long long acc[16])
{
    const float4* fr = (const float4*)frow;
    float4 f0 = __ldg(fr + 0), f1 = __ldg(fr + 1);
    float4 f2 = __ldg(fr + 2), f3 = __ldg(fr + 3);
    float4 f4 = __ldg(fr + 4), f5 = __ldg(fr + 5);
    float4 f6 = __ldg(fr + 6), f7 = __ldg(fr + 7);
    float fv[32] = {
        f0.x, f0.y, f0.z, f0.w, f1.x, f1.y, f1.z, f1.w,
        f2.x, f2.y, f2.z, f2.w, f3.x, f3.y, f3.z, f3.w,
        f4.x, f4.y, f4.z, f4.w, f5.x, f5.y, f5.z, f5.w,
        f6.x, f6.y, f6.z, f6.w, f7.x, f7.y, f7.z, f7.w };
#pragma unroll
    for (int cin = 0; cin < 32; cin++) {
        unsigned long long bc;
        PACK2(bc, fv[cin]);
        const ulonglong2* wv = (const ulonglong2*)(wbase + cin * 16);
#pragma unroll
        for (int h = 0; h < 8; h++) {
            ulonglong2 wp = wv[h];
            FMA2(acc[2 * h],     bc, wp.x, acc[2 * h]);
            FMA2(acc[2 * h + 1], bc, wp.y, acc[2 * h + 1]);
        }
    }
}

// ============================================================
// 1. prep: reset counters + BN sums, scatter lookup
// ============================================================
__global__ void prep_kernel(const int4* __restrict__ coords) {
    int i = blockIdx.x * blockDim.x + threadIdx.x;
    if (i < 8) d_cnt[i] = 0;
    if (i >= 8 && i < 72) d_sums[i - 8] = 0.0f;
    if (i < NPTS) {
        int4 c = coords[i];
        d_lookup[((c.x * SX + c.y) * SY + c.z) * SZ + c.w] = i + 1;
    }
}

// ============================================================
// 2. probe: per-k pair lists + flags + zero flagged out rows
// ============================================================
__global__ __launch_bounds__(256) void probe_kernel(const int4* __restrict__ coords,
                                                    float* __restrict__ out) {
    __shared__ int s_wcnt[8][8];
    __shared__ int s_wbase[8][8];
    int tid  = threadIdx.x;
    int lane = tid & 31;
    int warp = tid >> 5;
    int pt = blockIdx.x * 256 + tid;
    bool act = pt < NPTS;

    int4 cc = act ? coords[pt] : make_int4(0, 1, 0, 1);
    int base = ((cc.x * SX + cc.y) * SY + cc.z) * SZ + cc.w;

    unsigned mask = 0;
    int nb[8];
#pragma unroll
    for (int k = 0; k < 9; k++) {
        if (k == 4) continue;
        int d0 = k / 3 - 1, d2 = k % 3 - 1;
        int n0 = cc.y + d0, n2 = cc.w + d2;
        bool valid = act && (n0 >= 0) && (n0 < SX) && (n2 >= 0) && (n2 < SZ);
        int idx = valid ? (base + d0 * (SY * SZ) + d2) : 0;
        int j = valid ? __ldg(&d_lookup[idx]) : 0;
        int ki = (k < 4) ? k : k - 1;
        nb[ki] = j - 1;
        if (j > 0) mask |= (1u << ki);
    }

    if (act) d_flag[pt] = (unsigned char)(mask ? 1 : 0);

    // cooperative zero of flagged rows (these receive red.adds)
    {
        unsigned fb = __ballot_sync(0xffffffffu, act && mask);
        int wbase_pt = blockIdx.x * 256 + warp * 32;
        while (fb) {
            int p = __ffs(fb) - 1;
            fb &= fb - 1;
            out[(long long)(wbase_pt + p) * CCH + lane] = 0.0f;
        }
    }

    unsigned bal[8];
#pragma unroll
    for (int ki = 0; ki < 8; ki++)
        bal[ki] = __ballot_sync(0xffffffffu, (mask >> ki) & 1u);
    if (lane == 0) {
#pragma unroll
        for (int ki = 0; ki < 8; ki++)
            s_wcnt[ki][warp] = __popc(bal[ki]);
    }
    __syncthreads();
    if (tid < 8) {
        int run = 0;
#pragma unroll
        for (int w = 0; w < 8; w++) {
            int c = s_wcnt[tid][w];
            s_wbase[tid][w] = run;
            run += c;
        }
        int g = atomicAdd(&d_cnt[tid], run);
#pragma unroll
        for (int w = 0; w < 8; w++)
            s_wbase[tid][w] += g;
    }
    __syncthreads();
#pragma unroll
    for (int ki = 0; ki < 8; ki++) {
        if ((mask >> ki) & 1u) {
            int rank = __popc(bal[ki] & ((1u << lane) - 1u));
            d_pairs[ki][s_wbase[ki][warp] + rank] = make_int2(pt, nb[ki]);
        }
    }
}

// ============================================================
// 3. neighbor conv: grid.y = ki, one thread per pair, uniform-k
// ============================================================
__global__ __launch_bounds__(256) void neighbor_kernel(
    const float* __restrict__ feat,
    const float* __restrict__ weight,
    float*       __restrict__ out)
{
    int ki = blockIdx.y;
    int k  = (ki < 4) ? ki : ki + 1;
    __shared__ unsigned long long w2[512];
    {
        const unsigned long long* ws =
            (const unsigned long long*)(weight + k * 1024);
        for (int i = threadIdx.x; i < 512; i += 256)
            w2[i] = ws[i];
    }
    __syncthreads();

    int n = d_cnt[ki];
    for (int p = blockIdx.x * 256 + threadIdx.x; p < n; p += gridDim.x * 256) {
        int2 pr = d_pairs[ki][p];
        unsigned long long acc[16];
#pragma unroll
        for (int q = 0; q < 16; q++) acc[q] = 0ull;
        gemv_accum(feat + (long long)pr.y * CCH, w2, acc);

        float* orow = out + (long long)pr.x * CCH;
#pragma unroll
        for (int h = 0; h < 8; h++) {
            unsigned int u0, u1, u2, u3;
            UNPACK2(u0, u1, acc[2 * h]);
            UNPACK2(u2, u3, acc[2 * h + 1]);
            asm volatile("red.global.add.v4.f32 [%0], {%1, %2, %3, %4};"
                         :: "l"(orow + 4 * h),
                            "f"(__uint_as_float(u0)), "f"(__uint_as_float(u1)),
                            "f"(__uint_as_float(u2)), "f"(__uint_as_float(u3))
                         : "memory");
        }
    }
}

// ============================================================
// 4. self conv via mma.sync bf16 3-split (M=128, N=32, K=96)
//    + partial add + LeakyReLU + BN reduce
//    A row: [xh(32) | xl(32) | xh(32)], B row (per cout): [wh | wh | wl]
// ============================================================
#define ASTR 104      // bf16 elements per smem row (208 B; 13*16B -> ldmatrix conflict-free)
#define BPTS 128

__global__ __launch_bounds__(256) void selfleaky_mma_kernel(
    const float* __restrict__ feat,
    const float* __restrict__ weight,
    float*       __restrict__ out)
{
    __shared__ __align__(16) __nv_bfloat16 s_A[BPTS * ASTR];  // 26624 B
    __shared__ __align__(16) __nv_bfloat16 s_B[32 * ASTR];    //  6656 B
    __shared__ unsigned char s_flag[BPTS];
    __shared__ float s_sum[32], s_sq[32];
    float* s_out = (float*)s_A;   // overlay after MMA (128*36*4 = 18432 B)

    int tid  = threadIdx.x;
    int wrp  = tid >> 5;
    int lane = tid & 31;
    int blk0 = blockIdx.x * BPTS;
    int gbase = blk0 * 8;

    if (tid < 32) { s_sum[tid] = 0.0f; s_sq[tid] = 0.0f; }
    if (tid < BPTS) s_flag[tid] = d_flag[blk0 + tid];

    // ---- stage A: coalesced LDG.128, bf16 split, 3 regions ----
    {
        const float4* f4 = (const float4*)feat;
#pragma unroll
        for (int i = 0; i < 4; i++) {
            int idx = i * 256 + tid;               // 0..1023
            float4 v = __ldg(f4 + gbase + idx);
            int r  = idx >> 3;
            int c4 = (idx & 7) << 2;
            __nv_bfloat162 h01 = __floats2bfloat162_rn(v.x, v.y);
            __nv_bfloat162 h23 = __floats2bfloat162_rn(v.z, v.w);
            __nv_bfloat162 l01 = __floats2bfloat162_rn(
                v.x - __bfloat162float(h01.x), v.y - __bfloat162float(h01.y));
            __nv_bfloat162 l23 = __floats2bfloat162_rn(
                v.z - __bfloat162float(h23.x), v.w - __bfloat162float(h23.y));
            __nv_bfloat162* row = (__nv_bfloat162*)&s_A[r * ASTR];
            row[(c4 >> 1) + 0]  = h01;
            row[(c4 >> 1) + 1]  = h23;
            row[(c4 >> 1) + 16] = l01;   // cols +32
            row[(c4 >> 1) + 17] = l23;
            row[(c4 >> 1) + 32] = h01;   // cols +64 (xh dup)
            row[(c4 >> 1) + 33] = h23;
        }
    }

    // ---- stage B: weights k=4, transpose to [cout][cin-ext] ----
    {
        float4 wv = __ldg((const float4*)(weight + 4 * 1024) + tid);
        int el  = tid * 4;
        int cin = el >> 5;
        int n0  = el & 31;
        float wf[4] = { wv.x, wv.y, wv.z, wv.w };
#pragma unroll
        for (int j = 0; j < 4; j++) {
            int n = n0 + j;
            __nv_bfloat16 wh = __float2bfloat16(wf[j]);
            __nv_bfloat16 wl = __float2bfloat16(wf[j] - __bfloat162float(wh));
            s_B[n * ASTR + cin]      = wh;
            s_B[n * ASTR + 32 + cin] = wh;
            s_B[n * ASTR + 64 + cin] = wl;
        }
    }
    __syncthreads();

    // ---- warp MMA: warp wrp owns rows [16*wrp, 16*wrp+16) ----
    float c0[4] = {0,0,0,0}, c1[4] = {0,0,0,0},
          c2[4] = {0,0,0,0}, c3[4] = {0,0,0,0};
    {
        uint32_t a_base = smem_u32(s_A) + (wrp * 16 + (lane & 15)) * (ASTR * 2)
                        + ((lane >> 4) * 8) * 2;
        uint32_t b_base0 = smem_u32(s_B) + (lane & 15) * (ASTR * 2)
                         + ((lane >> 4) * 8) * 2;
        uint32_t b_base1 = b_base0 + 16 * (ASTR * 2);
#pragma unroll
        for (int s = 0; s < 6; s++) {
            uint32_t koff = s * 32;   // 16 bf16 per k-step
            uint32_t a0, a1, a2, a3, p0, p1, p2, p3, q0, q1, q2, q3;
            LDSM_X4(a0, a1, a2, a3, a_base + koff);
            LDSM_X4(p0, p1, p2, p3, b_base0 + koff);
            LDSM_X4(q0, q1, q2, q3, b_base1 + koff);
            MMA_BF16(c0, a0, a1, a2, a3, p0, p2);   // couts 0-7
            MMA_BF16(c1, a0, a1, a2, a3, p1, p3);   // couts 8-15
            MMA_BF16(c2, a0, a1, a2, a3, q0, q2);   // couts 16-23
            MMA_BF16(c3, a0, a1, a2, a3, q1, q3);   // couts 24-31
        }
    }
    __syncthreads();   // all ldmatrix reads of s_A done before overlay write

    // ---- epilogue: acc regs -> s_out[row][col] (stride 36) ----
    {
        int g  = lane >> 2;
        int tg = lane & 3;
        int r0 = wrp * 16 + g;
        float* cs[4] = { c0, c1, c2, c3 };
#pragma unroll
        for (int j = 0; j < 4; j++) {
            int col = 8 * j + 2 * tg;
            s_out[r0 * 36 + col]       = cs[j][0];
            s_out[r0 * 36 + col + 1]   = cs[j][1];
            s_out[(r0+8) * 36 + col]   = cs[j][2];
            s_out[(r0+8) * 36 + col+1] = cs[j][3];
        }
    }
    __syncthreads();

    // ---- fused writeback: +partials, leaky, store, BN accumulate ----
    float bs0 = 0.f, bs1 = 0.f, bs2 = 0.f, bs3 = 0.f;
    float bq0 = 0.f, bq1 = 0.f, bq2 = 0.f, bq3 = 0.f;
    {
        float4* o4 = (float4*)out;
#pragma unroll
        for (int i = 0; i < 4; i++) {
            int idx = i * 256 + tid;
            int r = idx >> 3;
            int c = (idx & 7) << 2;
            float4 v = *(const float4*)&s_out[r * 36 + c];
            if (s_flag[r]) {
                float4 p = __ldg(o4 + gbase + idx);
                v.x += p.x; v.y += p.y; v.z += p.z; v.w += p.w;
            }
            v.x = fmaxf(v.x, 0.01f * v.x);
            v.y = fmaxf(v.y, 0.01f * v.y);
            v.z = fmaxf(v.z, 0.01f * v.z);
            v.w = fmaxf(v.w, 0.01f * v.w);
            o4[gbase + idx] = v;
            bs0 += v.x; bq0 = fmaf(v.x, v.x, bq0);
            bs1 += v.y; bq1 = fmaf(v.y, v.y, bq1);
            bs2 += v.z; bq2 = fmaf(v.z, v.z, bq2);
            bs3 += v.w; bq3 = fmaf(v.w, v.w, bq3);
        }
    }
    {
        int cq = (tid & 7) * 4;
        atomicAdd(&s_sum[cq + 0], bs0);
        atomicAdd(&s_sum[cq + 1], bs1);
        atomicAdd(&s_sum[cq + 2], bs2);
        atomicAdd(&s_sum[cq + 3], bs3);
        atomicAdd(&s_sq[cq + 0], bq0);
        atomicAdd(&s_sq[cq + 1], bq1);
        atomicAdd(&s_sq[cq + 2], bq2);
        atomicAdd(&s_sq[cq + 3], bq3);
    }
    __syncthreads();
    if (tid < 32) {
        atomicAdd(&d_sums[tid],      s_sum[tid]);
        atomicAdd(&d_sums[32 + tid], s_sq[tid]);
    }
}

// ============================================================
// 5. normalize in place; scale/shift computed per block (fused finalize)
// ============================================================
__global__ __launch_bounds__(256) void norm_kernel(float4* __restrict__ y,
                                                   const float* __restrict__ gamma,
                                                   const float* __restrict__ beta) {
    __shared__ float s_sc[32], s_sh[32];
    if (threadIdx.x < 32) {
        int c = threadIdx.x;
        const float invN = 1.0f / (float)NPTS;
        float sum = __ldg(&d_sums[c]);
        float sq  = __ldg(&d_sums[32 + c]);
        float mean = sum * invN;
        float var  = sq * invN - mean * mean;
        float sc   = __ldg(&gamma[c]) * rsqrtf(var + EPSV);
        s_sc[c] = sc;
        s_sh[c] = __ldg(&beta[c]) - mean * sc;
    }
    __syncthreads();
    int base = blockIdx.x * 1024;
#pragma unroll
    for (int i = 0; i < 4; i++) {
        int t = base + i * 256 + threadIdx.x;    // total = 3.2M, grid exact
        int c0 = (t & 7) * 4;
        float4 v = y[t];
        v.x = fmaf(v.x, s_sc[c0 + 0], s_sh[c0 + 0]);
        v.y = fmaf(v.y, s_sc[c0 + 1], s_sh[c0 + 1]);
        v.z = fmaf(v.z, s_sc[c0 + 2], s_sh[c0 + 2]);
        v.w = fmaf(v.w, s_sc[c0 + 3], s_sh[c0 + 3]);
        y[t] = v;
    }
}

// ============================================================
extern "C" void kernel_launch(void* const* d_in, const int* in_sizes, int n_in,
                              void* d_out, int out_size) {
    const float* feat   = (const float*)d_in[0];
    const int4*  coords = (const int4*)d_in[1];
    const float* weight = (const float*)d_in[2];
    const float* gamma  = (const float*)d_in[3];
    const float* beta   = (const float*)d_in[4];
    float* out = (float*)d_out;

    prep_kernel<<<(NPTS + 255) / 256, 256>>>(coords);
    probe_kernel<<<(NPTS + 255) / 256, 256>>>(coords, out);
    neighbor_kernel<<<dim3(64, 8), 256>>>(feat, weight, out);
    selfleaky_mma_kernel<<<NPTS / BPTS, 256>>>(feat, weight, out);
    norm_kernel<<<NPTS * 8 / 1024, 256>>>((float4*)out, gamma, beta);
}

// round 11
// speedup vs baseline: 1.2072x; 1.0003x over previous
#include <cuda_runtime.h>
#include <cuda_bf16.h>
#include <cstdint>

#define NPTS 400000
#define CCH  32
#define SX   480
#define SY   360
#define SZ   32
#define BB   2
#define LOOKUP_SIZE (BB*SX*SY*SZ)
#define EPSV 1e-5f

// ---- static scratch (no allocations allowed) ----
__device__ int   d_lookup[LOOKUP_SIZE];          // cell -> idx+1, 0 = empty (persistent)
__device__ __align__(16) float d_sums[64];       // [0:32) sum, [32:64) sumsq
__device__ int   d_cnt[8];                       // per-k pair counts (k != 4)
__device__ int2  d_pairs[8][NPTS];               // (out_pt, in_pt) per k
__device__ unsigned char d_flag[NPTS];           // point has >=1 valid neighbor

// ---- packed fp32x2 helpers (neighbor kernel) ----
#define FMA2(d, a, b, c) \
    asm("fma.rn.f32x2 %0, %1, %2, %3;" : "=l"(d) : "l"(a), "l"(b), "l"(c))
#define PACK2(d, x) \
    asm("mov.b64 %0, {%1, %1};" : "=l"(d) : "r"(__float_as_uint(x)))
#define UNPACK2(lo, hi, a) \
    asm("mov.b64 {%0, %1}, %2;" : "=r"(lo), "=r"(hi) : "l"(a))

__device__ __forceinline__ uint32_t smem_u32(const void* p) {
    uint32_t a;
    asm("{ .reg .u64 t; cvta.to.shared.u64 t, %1; cvt.u32.u64 %0, t; }"
        : "=r"(a) : "l"(p));
    return a;
}

#define LDSM_X4(r0, r1, r2, r3, addr) \
    asm volatile("ldmatrix.sync.aligned.m8n8.x4.shared.b16 {%0,%1,%2,%3}, [%4];" \
                 : "=r"(r0), "=r"(r1), "=r"(r2), "=r"(r3) : "r"(addr))

#define MMA_BF16(c, a0, a1, a2, a3, b0, b1) \
    asm volatile("mma.sync.aligned.m16n8k16.row.col.f32.bf16.bf16.f32 " \
                 "{%0,%1,%2,%3}, {%4,%5,%6,%7}, {%8,%9}, {%0,%1,%2,%3};" \
                 : "+f"(c[0]), "+f"(c[1]), "+f"(c[2]), "+f"(c[3]) \
                 : "r"(a0), "r"(a1), "r"(a2), "r"(a3), "r"(b0), "r"(b1))

// ============================================================
// GEMV core from global feat row (used by neighbor kernel)
// ============================================================
__device__ __forceinline__ void gemv_accum(
    const float* __restrict__ frow,
    const unsigned long long* __restrict__ wbase,
    unsigned long long acc[16])
{
    const float4* fr = (const float4*)frow;
    float4 f0 = __ldg(fr + 0), f1 = __ldg(fr + 1);
    float4 f2 = __ldg(fr + 2), f3 = __ldg(fr + 3);
    float4 f4 = __ldg(fr + 4), f5 = __ldg(fr + 5);
    float4 f6 = __ldg(fr + 6), f7 = __ldg(fr + 7);
    float fv[32] = {
        f0.x, f0.y, f0.z, f0.w, f1.x, f1.y, f1.z, f1.w,
        f2.x, f2.y, f2.z, f2.w, f3.x, f3.y, f3.z, f3.w,
        f4.x, f4.y, f4.z, f4.w, f5.x, f5.y, f5.z, f5.w,
        f6.x, f6.y, f6.z, f6.w, f7.x, f7.y, f7.z, f7.w };
#pragma unroll
    for (int cin = 0; cin < 32; cin++) {
        unsigned long long bc;
        PACK2(bc, fv[cin]);
        const ulonglong2* wv = (const ulonglong2*)(wbase + cin * 16);
#pragma unroll
        for (int h = 0; h < 8; h++) {
            ulonglong2 wp = wv[h];
            FMA2(acc[2 * h],     bc, wp.x, acc[2 * h]);
            FMA2(acc[2 * h + 1], bc, wp.y, acc[2 * h + 1]);
        }
    }
}

// ============================================================
// 1. prep: reset counters + BN sums, scatter lookup
// ============================================================
__global__ void prep_kernel(const int4* __restrict__ coords) {
    int i = blockIdx.x * blockDim.x + threadIdx.x;
    if (i < 8) d_cnt[i] = 0;
    if (i >= 8 && i < 72) d_sums[i - 8] = 0.0f;
    if (i < NPTS) {
        int4 c = coords[i];
        d_lookup[((c.x * SX + c.y) * SY + c.z) * SZ + c.w] = i + 1;
    }
}

// ============================================================
// 2. probe: per-k pair lists + flags + zero flagged out rows
// ============================================================
__global__ __launch_bounds__(256) void probe_kernel(const int4* __restrict__ coords,
                                                    float* __restrict__ out) {
    __shared__ int s_wcnt[8][8];
    __shared__ int s_wbase[8][8];
    int tid  = threadIdx.x;
    int lane = tid & 31;
    int warp = tid >> 5;
    int pt = blockIdx.x * 256 + tid;
    bool act = pt < NPTS;

    int4 cc = act ? coords[pt] : make_int4(0, 1, 0, 1);
    int base = ((cc.x * SX + cc.y) * SY + cc.z) * SZ + cc.w;

    unsigned mask = 0;
    int nb[8];
#pragma unroll
    for (int k = 0; k < 9; k++) {
        if (k == 4) continue;
        int d0 = k / 3 - 1, d2 = k % 3 - 1;
        int n0 = cc.y + d0, n2 = cc.w + d2;
        bool valid = act && (n0 >= 0) && (n0 < SX) && (n2 >= 0) && (n2 < SZ);
        int idx = valid ? (base + d0 * (SY * SZ) + d2) : 0;
        int j = valid ? __ldg(&d_lookup[idx]) : 0;
        int ki = (k < 4) ? k : k - 1;
        nb[ki] = j - 1;
        if (j > 0) mask |= (1u << ki);
    }

    if (act) d_flag[pt] = (unsigned char)(mask ? 1 : 0);

    // cooperative zero of flagged rows (these receive red.adds)
    {
        unsigned fb = __ballot_sync(0xffffffffu, act && mask);
        int wbase_pt = blockIdx.x * 256 + warp * 32;
        while (fb) {
            int p = __ffs(fb) - 1;
            fb &= fb - 1;
            out[(long long)(wbase_pt + p) * CCH + lane] = 0.0f;
        }
    }

    unsigned bal[8];
#pragma unroll
    for (int ki = 0; ki < 8; ki++)
        bal[ki] = __ballot_sync(0xffffffffu, (mask >> ki) & 1u);
    if (lane == 0) {
#pragma unroll
        for (int ki = 0; ki < 8; ki++)
            s_wcnt[ki][warp] = __popc(bal[ki]);
    }
    __syncthreads();
    if (tid < 8) {
        int run = 0;
#pragma unroll
        for (int w = 0; w < 8; w++) {
            int c = s_wcnt[tid][w];
            s_wbase[tid][w] = run;
            run += c;
        }
        int g = atomicAdd(&d_cnt[tid], run);
#pragma unroll
        for (int w = 0; w < 8; w++)
            s_wbase[tid][w] += g;
    }
    __syncthreads();
#pragma unroll
    for (int ki = 0; ki < 8; ki++) {
        if ((mask >> ki) & 1u) {
            int rank = __popc(bal[ki] & ((1u << lane) - 1u));
            d_pairs[ki][s_wbase[ki][warp] + rank] = make_int2(pt, nb[ki]);
        }
    }
}

// ============================================================
// 3. neighbor conv: grid.y = ki, one thread per pair, uniform-k
// ============================================================
__global__ __launch_bounds__(256) void neighbor_kernel(
    const float* __restrict__ feat,
    const float* __restrict__ weight,
    float*       __restrict__ out)
{
    int ki = blockIdx.y;
    int k  = (ki < 4) ? ki : ki + 1;
    __shared__ unsigned long long w2[512];
    {
        const unsigned long long* ws =
            (const unsigned long long*)(weight + k * 1024);
        for (int i = threadIdx.x; i < 512; i += 256)
            w2[i] = ws[i];
    }
    __syncthreads();

    int n = d_cnt[ki];
    for (int p = blockIdx.x * 256 + threadIdx.x; p < n; p += gridDim.x * 256) {
        int2 pr = d_pairs[ki][p];
        unsigned long long acc[16];
#pragma unroll
        for (int q = 0; q < 16; q++) acc[q] = 0ull;
        gemv_accum(feat + (long long)pr.y * CCH, w2, acc);

        float* orow = out + (long long)pr.x * CCH;
#pragma unroll
        for (int h = 0; h < 8; h++) {
            unsigned int u0, u1, u2, u3;
            UNPACK2(u0, u1, acc[2 * h]);
            UNPACK2(u2, u3, acc[2 * h + 1]);
            asm volatile("red.global.add.v4.f32 [%0], {%1, %2, %3, %4};"
                         :: "l"(orow + 4 * h),
                            "f"(__uint_as_float(u0)), "f"(__uint_as_float(u1)),
                            "f"(__uint_as_float(u2)), "f"(__uint_as_float(u3))
                         : "memory");
        }
    }
}

// ============================================================
// 4. self conv via mma.sync bf16 3-product split (M=128, N=32)
//    A tile: [xh(32) | xl(32)] (K=64); B tile: [wh | wh | wl]
//    products: xh*wh + xl*wh (k-steps 0-3) + xh*wl (A steps 0-1, B steps 4-5)
// ============================================================
#define ASTR 72       // bf16/row: 144 B = 9 x 16B (odd) -> ldmatrix conflict-free
#define BSTR 104      // bf16/row: 208 B = 13 x 16B (odd)
#define BPTS 128

__global__ __launch_bounds__(256) void selfleaky_mma_kernel(
    const float* __restrict__ feat,
    const float* __restrict__ weight,
    float*       __restrict__ out)
{
    __shared__ __align__(16) __nv_bfloat16 s_A[BPTS * ASTR];  // 18432 B
    __shared__ __align__(16) __nv_bfloat16 s_B[32 * BSTR];    //  6656 B
    __shared__ unsigned char s_flag[BPTS];
    __shared__ float s_sum[32], s_sq[32];
    float* s_out = (float*)s_A;   // overlay after MMA: 128*36*4 = 18432 B exact

    int tid  = threadIdx.x;
    int wrp  = tid >> 5;
    int lane = tid & 31;
    int blk0 = blockIdx.x * BPTS;
    int gbase = blk0 * 8;

    if (tid < 32) { s_sum[tid] = 0.0f; s_sq[tid] = 0.0f; }
    if (tid < BPTS) s_flag[tid] = d_flag[blk0 + tid];

    // ---- stage A: coalesced LDG.128, bf16 split, 2 regions, STS.64 ----
    {
        const float4* f4 = (const float4*)feat;
#pragma unroll
        for (int i = 0; i < 4; i++) {
            int idx = i * 256 + tid;               // 0..1023
            float4 v = __ldg(f4 + gbase + idx);
            int r  = idx >> 3;
            int c4 = (idx & 7) << 2;               // bf16 col: 0,4,..28
            __nv_bfloat162 h01 = __floats2bfloat162_rn(v.x, v.y);
            __nv_bfloat162 h23 = __floats2bfloat162_rn(v.z, v.w);
            __nv_bfloat162 l01 = __floats2bfloat162_rn(
                v.x - __bfloat162float(h01.x), v.y - __bfloat162float(h01.y));
            __nv_bfloat162 l23 = __floats2bfloat162_rn(
                v.z - __bfloat162float(h23.x), v.w - __bfloat162float(h23.y));
            uint2 hh = make_uint2(*(uint32_t*)&h01, *(uint32_t*)&h23);
            uint2 ll = make_uint2(*(uint32_t*)&l01, *(uint32_t*)&l23);
            *(uint2*)&s_A[r * ASTR + c4]      = hh;   // xh cols 0..31
            *(uint2*)&s_A[r * ASTR + 32 + c4] = ll;   // xl cols 32..63
        }
    }

    // ---- stage B: weights k=4, transpose to [cout][wh|wh|wl] ----
    {
        float4 wv = __ldg((const float4*)(weight + 4 * 1024) + tid);
        int el  = tid * 4;
        int cin = el >> 5;
        int n0  = el & 31;
        float wf[4] = { wv.x, wv.y, wv.z, wv.w };
#pragma unroll
        for (int j = 0; j < 4; j++) {
            int n = n0 + j;
            __nv_bfloat16 wh = __float2bfloat16(wf[j]);
            __nv_bfloat16 wl = __float2bfloat16(wf[j] - __bfloat162float(wh));
            s_B[n * BSTR + cin]      = wh;
            s_B[n * BSTR + 32 + cin] = wh;
            s_B[n * BSTR + 64 + cin] = wl;
        }
    }
    __syncthreads();

    // ---- warp MMA: warp wrp owns rows [16*wrp, 16*wrp+16) ----
    float c0[4] = {0,0,0,0}, c1[4] = {0,0,0,0},
          c2[4] = {0,0,0,0}, c3[4] = {0,0,0,0};
    {
        uint32_t a_base = smem_u32(s_A) + ((wrp * 16 + (lane & 15)) * ASTR
                        + (lane >> 4) * 8) * 2;
        uint32_t b_base0 = smem_u32(s_B) + ((lane & 15) * BSTR
                         + (lane >> 4) * 8) * 2;
        uint32_t b_base1 = b_base0 + 16 * BSTR * 2;
#pragma unroll
        for (int s = 0; s < 6; s++) {
            uint32_t a_koff = (s < 4 ? s : s - 4) * 32;   // bytes (16 bf16)
            uint32_t b_koff = s * 32;
            uint32_t a0, a1, a2, a3, p0, p1, p2, p3, q0, q1, q2, q3;
            LDSM_X4(a0, a1, a2, a3, a_base + a_koff);
            LDSM_X4(p0, p1, p2, p3, b_base0 + b_koff);
            LDSM_X4(q0, q1, q2, q3, b_base1 + b_koff);
            MMA_BF16(c0, a0, a1, a2, a3, p0, p2);   // couts 0-7
            MMA_BF16(c1, a0, a1, a2, a3, p1, p3);   // couts 8-15
            MMA_BF16(c2, a0, a1, a2, a3, q0, q2);   // couts 16-23
            MMA_BF16(c3, a0, a1, a2, a3, q1, q3);   // couts 24-31
        }
    }
    __syncthreads();   // all ldmatrix reads of s_A done before overlay write

    // ---- epilogue: acc regs -> s_out[row][col] (stride 36), st.v2 ----
    {
        int g  = lane >> 2;
        int tg = lane & 3;
        int r0 = wrp * 16 + g;
        float* cs[4] = { c0, c1, c2, c3 };
#pragma unroll
        for (int j = 0; j < 4; j++) {
            int col = 8 * j + 2 * tg;
            *(float2*)&s_out[r0 * 36 + col]       = make_float2(cs[j][0], cs[j][1]);
            *(float2*)&s_out[(r0 + 8) * 36 + col] = make_float2(cs[j][2], cs[j][3]);
        }
    }
    __syncthreads();

    // ---- fused writeback: +partials, leaky, store, BN accumulate ----
    float bs0 = 0.f, bs1 = 0.f, bs2 = 0.f, bs3 = 0.f;
    float bq0 = 0.f, bq1 = 0.f, bq2 = 0.f, bq3 = 0.f;
    {
        float4* o4 = (float4*)out;
#pragma unroll
        for (int i = 0; i < 4; i++) {
            int idx = i * 256 + tid;
            int r = idx >> 3;
            int c = (idx & 7) << 2;
            float4 v = *(const float4*)&s_out[r * 36 + c];
            if (s_flag[r]) {
                float4 p = __ldg(o4 + gbase + idx);
                v.x += p.x; v.y += p.y; v.z += p.z; v.w += p.w;
            }
            v.x = fmaxf(v.x, 0.01f * v.x);
            v.y = fmaxf(v.y, 0.01f * v.y);
            v.z = fmaxf(v.z, 0.01f * v.z);
            v.w = fmaxf(v.w, 0.01f * v.w);
            o4[gbase + idx] = v;
            bs0 += v.x; bq0 = fmaf(v.x, v.x, bq0);
            bs1 += v.y; bq1 = fmaf(v.y, v.y, bq1);
            bs2 += v.z; bq2 = fmaf(v.z, v.z, bq2);
            bs3 += v.w; bq3 = fmaf(v.w, v.w, bq3);
        }
    }
    {
        int cq = (tid & 7) * 4;
        atomicAdd(&s_sum[cq + 0], bs0);
        atomicAdd(&s_sum[cq + 1], bs1);
        atomicAdd(&s_sum[cq + 2], bs2);
        atomicAdd(&s_sum[cq + 3], bs3);
        atomicAdd(&s_sq[cq + 0], bq0);
        atomicAdd(&s_sq[cq + 1], bq1);
        atomicAdd(&s_sq[cq + 2], bq2);
        atomicAdd(&s_sq[cq + 3], bq3);
    }
    __syncthreads();
    if (tid < 32) {
        atomicAdd(&d_sums[tid],      s_sum[tid]);
        atomicAdd(&d_sums[32 + tid], s_sq[tid]);
    }
}

// ============================================================
// 5. normalize in place; scale/shift computed per block (fused finalize)
// ============================================================
__global__ __launch_bounds__(256) void norm_kernel(float4* __restrict__ y,
                                                   const float* __restrict__ gamma,
                                                   const float* __restrict__ beta) {
    __shared__ float s_sc[32], s_sh[32];
    if (threadIdx.x < 32) {
        int c = threadIdx.x;
        const float invN = 1.0f / (float)NPTS;
        float sum = __ldg(&d_sums[c]);
        float sq  = __ldg(&d_sums[32 + c]);
        float mean = sum * invN;
        float var  = sq * invN - mean * mean;
        float sc   = __ldg(&gamma[c]) * rsqrtf(var + EPSV);
        s_sc[c] = sc;
        s_sh[c] = __ldg(&beta[c]) - mean * sc;
    }
    __syncthreads();
    int base = blockIdx.x * 1024;
#pragma unroll
    for (int i = 0; i < 4; i++) {
        int t = base + i * 256 + threadIdx.x;    // total = 3.2M, grid exact
        int c0 = (t & 7) * 4;
        float4 v = y[t];
        v.x = fmaf(v.x, s_sc[c0 + 0], s_sh[c0 + 0]);
        v.y = fmaf(v.y, s_sc[c0 + 1], s_sh[c0 + 1]);
        v.z = fmaf(v.z, s_sc[c0 + 2], s_sh[c0 + 2]);
        v.w = fmaf(v.w, s_sc[c0 + 3], s_sh[c0 + 3]);
        y[t] = v;
    }
}

// ============================================================
extern "C" void kernel_launch(void* const* d_in, const int* in_sizes, int n_in,
                              void* d_out, int out_size) {
    const float* feat   = (const float*)d_in[0];
    const int4*  coords = (const int4*)d_in[1];
    const float* weight = (const float*)d_in[2];
    const float* gamma  = (const float*)d_in[3];
    const float* beta   = (const float*)d_in[4];
    float* out = (float*)d_out;

    prep_kernel<<<(NPTS + 255) / 256, 256>>>(coords);
    probe_kernel<<<(NPTS + 255) / 256, 256>>>(coords, out);
    neighbor_kernel<<<dim3(64, 8), 256>>>(feat, weight, out);
    selfleaky_mma_kernel<<<NPTS / BPTS, 256>>>(feat, weight, out);
    norm_kernel<<<NPTS * 8 / 1024, 256>>>((float4*)out, gamma, beta);
}